// round 17
// baseline (speedup 1.0000x reference)
#include <cuda_runtime.h>
#include <cstdint>

// M=8192 rows, N=8192 cols, H=4096.
//   xf    = x * weight_scale[0] * activation_scale[row]
//   sw    = front * (back * sigmoid(back)),  s = sw * quant_scale[0]
//   scale = rowmax(|s|)/127;  i8 = clip(rint(s/scale), -128, 127)  (0 if scale<=0)
// Output (float32): [ i8 as float : M*H ][ scale : M ]
//
// R16: continue the measured geometry gradient — ONE row per CTA at 1024
// threads, 4 elements/thread (1 front float4 + 1 back float4). R13 showed
// halving the per-thread serial chain bought 3.4us (65.5->62.0); this is
// the next halving. Same cache policies (__ldcs/__stcs), same redux+ONE-
// barrier reduce, single-row barrier domain, occ 2x1024 = full.

#define M_ROWS 8192
#define N_COLS 8192
#define H_COLS 4096
#define BLOCK_THREADS 1024
#define N_WARPS (BLOCK_THREADS / 32)   // 32

__global__ __launch_bounds__(BLOCK_THREADS, 2)
void swiglu_quant_kernel(const float* __restrict__ x,
                         const float* __restrict__ weight_scale,
                         const float* __restrict__ activation_scale,
                         const float* __restrict__ quant_scale,
                         float* __restrict__ out) {
    const int row = blockIdx.x;
    const int tid = threadIdx.x;

    __shared__ __align__(16) float warp_max[N_WARPS];

    const float c = weight_scale[0] * activation_scale[row];
    const float q = quant_scale[0];

    const float4* __restrict__ pf =
        reinterpret_cast<const float4*>(x + (size_t)row * N_COLS) + tid;
    const float4* __restrict__ pb = pf + (H_COLS / 4);

    // ---- load (2x LDG.128, streaming), SwiGLU, local absmax
    const float4 f = __ldcs(pf);
    const float4 b = __ldcs(pb);

    float s[4];
    float amax;
    {
        const float fl[4] = {f.x, f.y, f.z, f.w};
        const float bk[4] = {b.x, b.y, b.z, b.w};
        amax = 0.0f;
#pragma unroll
        for (int j = 0; j < 4; j++) {
            const float lin = fl[j] * c;
            const float g   = bk[j] * c;
            const float sig = 1.0f / (1.0f + __expf(-g));
            const float v   = lin * (g * sig) * q;
            s[j] = v;
            amax = fmaxf(amax, fabsf(v));
        }
    }

    // ---- absmax reduce: redux per warp, ONE barrier
    unsigned wmax = __reduce_max_sync(0xFFFFFFFFu, __float_as_uint(amax));
    if ((tid & 31) == 0) warp_max[tid >> 5] = __uint_as_float(wmax);
    __syncthreads();

    // vectorized fold: 8x LDS.128 + 31 max over the 32 warp maxima
    const float4* wv = reinterpret_cast<const float4*>(warp_max);
    float m;
    {
        float mm[8];
#pragma unroll
        for (int i = 0; i < 8; i++) {
            const float4 w = wv[i];
            mm[i] = fmaxf(fmaxf(w.x, w.y), fmaxf(w.z, w.w));
        }
        m = fmaxf(fmaxf(fmaxf(mm[0], mm[1]), fmaxf(mm[2], mm[3])),
                  fmaxf(fmaxf(mm[4], mm[5]), fmaxf(mm[6], mm[7])));
    }
    const float scale = m * (1.0f / 127.0f);
    const float inv   = (scale > 0.0f) ? (1.0f / scale) : 0.0f;

    // scale store first: scattered 4B STG drains under the STG.128 burst
    if (tid == 0) {
        out[(size_t)M_ROWS * H_COLS + row] = scale;
    }

    // ---- quantize + streaming store (no clamp: |s*inv| <= 127*(1+2ulp))
    float4* __restrict__ po =
        reinterpret_cast<float4*>(out + (size_t)row * H_COLS) + tid;
    float4 o;
    o.x = rintf(s[0] * inv);
    o.y = rintf(s[1] * inv);
    o.z = rintf(s[2] * inv);
    o.w = rintf(s[3] * inv);
    __stcs(po, o);
}

extern "C" void kernel_launch(void* const* d_in, const int* in_sizes, int n_in,
                              void* d_out, int out_size) {
    const float* x  = (const float*)d_in[0];
    const float* ws = (const float*)d_in[1];
    const float* as = (const float*)d_in[2];
    const float* qs = (const float*)d_in[3];
    float* out = (float*)d_out;
    (void)in_sizes; (void)n_in; (void)out_size;

    swiglu_quant_kernel<<<M_ROWS, BLOCK_THREADS>>>(x, ws, as, qs, out);
}